// round 9
// baseline (speedup 1.0000x reference)
#include <cuda_runtime.h>
#include <cuda_fp16.h>
#include <math.h>
#include <stdint.h>

#define Nn 4096
#define Hh 4
#define NWORDS 128   // Nn/32

// ---------------- scratch (static device globals; no allocation) -------------
__device__ uint32_t g_mask[Nn * NWORDS];          // 2 MB packed adjacency
__device__ float g_Wh[Hh * Nn * 64];              // fp32 Wh (for fe_kernel)
__device__ __half g_Wh16[Hh * Nn * 64];           // fp16 Wh (for agg cp.async)
__device__ float2 g_E1[Hh * Nn];                  // (e^f1, e^{0.2 f1}) per node
__device__ float2 g_E2[Hh * Nn];                  // (e^f2, e^{0.2 f2}) per node
__device__ float g_h1[Nn * 256];
__device__ float g_h2[Nn * 128];
__device__ float g_h3[Nn * 64];

static __device__ __forceinline__ uint32_t smem_cast(const void* p) {
    return (uint32_t)__cvta_generic_to_shared(p);
}

static __device__ __forceinline__ void ldsm_x4(uint32_t* r, uint32_t addr) {
    asm volatile("ldmatrix.sync.aligned.m8n8.x4.shared.b16 {%0,%1,%2,%3}, [%4];"
                 : "=r"(r[0]), "=r"(r[1]), "=r"(r[2]), "=r"(r[3]) : "r"(addr));
}

static __device__ __forceinline__ void ldsm_x4t(uint32_t* r, uint32_t addr) {
    asm volatile("ldmatrix.sync.aligned.m8n8.x4.trans.shared.b16 {%0,%1,%2,%3}, [%4];"
                 : "=r"(r[0]), "=r"(r[1]), "=r"(r[2]), "=r"(r[3]) : "r"(addr));
}

static __device__ __forceinline__ void cp_async16(uint32_t dst, const void* src) {
    asm volatile("cp.async.ca.shared.global [%0], [%1], 16;" :: "r"(dst), "l"(src));
}
static __device__ __forceinline__ void cp_commit() {
    asm volatile("cp.async.commit_group;");
}
static __device__ __forceinline__ void cp_wait0() {
    asm volatile("cp.async.wait_group 0;");
}

// ---------------- pack adjacency into bitmask --------------------------------
__global__ void pack_mask_kernel(const int* __restrict__ adj) {
    int idx = blockIdx.x * blockDim.x + threadIdx.x;  // one thread per 32-bit word
    int i = idx >> 7;
    int w = idx & 127;
    const int4* p = reinterpret_cast<const int4*>(adj + (size_t)i * Nn + (w << 5));
    uint32_t m = 0u;
#pragma unroll
    for (int q = 0; q < 8; q++) {
        int4 v = p[q];
        if (v.x) m |= 1u << (q * 4 + 0);
        if (v.y) m |= 1u << (q * 4 + 1);
        if (v.z) m |= 1u << (q * 4 + 2);
        if (v.w) m |= 1u << (q * 4 + 3);
    }
    g_mask[idx] = m;
}

// ---------------- Wh = x @ W[h]  (per head); writes fp32 + fp16 --------------
template <int FIN, int O, int TM, int TN>
__global__ __launch_bounds__(256) void gemm_wh_kernel(const float* __restrict__ x,
                                                      const float* __restrict__ W) {
    const int h = blockIdx.y;
    const int n0 = blockIdx.x * 128;
    const int t = threadIdx.x;
    __shared__ float xs[32][132];  // [f][row], padded, 16B-aligned rows
    __shared__ float ws[32][O];    // [f][o]
    const int CG = O / TN;
    const int rg = t / CG, cg = t % CG;
    float acc[TM][TN];
#pragma unroll
    for (int k = 0; k < TM; k++)
#pragma unroll
        for (int u = 0; u < TN; u++) acc[k][u] = 0.f;
    const float* Wc = W + (size_t)h * FIN * O;
    for (int f0 = 0; f0 < FIN; f0 += 32) {
        __syncthreads();
#pragma unroll
        for (int k = 0; k < 16; k++) {
            int idx = t + k * 256;
            int f = idx & 31, row = idx >> 5;
            xs[f][row] = x[(size_t)(n0 + row) * FIN + f0 + f];
        }
#pragma unroll
        for (int k = 0; k < (32 * O) / 256; k++) {
            int idx = t + k * 256;
            int o = idx % O, f = idx / O;
            ws[f][o] = Wc[(size_t)(f0 + f) * O + o];
        }
        __syncthreads();
#pragma unroll 8
        for (int f = 0; f < 32; f++) {
            float xv[TM], wv[TN];
#pragma unroll
            for (int q = 0; q < TM / 4; q++)
                *(float4*)&xv[q * 4] = *(const float4*)&xs[f][rg * TM + q * 4];
            if (TN >= 4) {
#pragma unroll
                for (int q = 0; q < TN / 4; q++)
                    *(float4*)&wv[q * 4] = *(const float4*)&ws[f][cg * TN + q * 4];
            } else {
                *(float2*)&wv[0] = *(const float2*)&ws[f][cg * TN];
            }
#pragma unroll
            for (int k = 0; k < TM; k++)
#pragma unroll
                for (int u = 0; u < TN; u++) acc[k][u] += xv[k] * wv[u];
        }
    }
#pragma unroll
    for (int k = 0; k < TM; k++) {
        int n = n0 + rg * TM + k;
#pragma unroll
        for (int u = 0; u < TN; u++) {
            size_t idx = ((size_t)h * Nn + n) * O + cg * TN + u;
            g_Wh[idx] = acc[k][u];
            g_Wh16[idx] = __float2half(acc[k][u]);
        }
    }
}

// ---------------- per-node attention scalars ---------------------------------
template <int O>
__global__ void fe_kernel(const float* __restrict__ a) {
    int idx = blockIdx.x * 256 + threadIdx.x;  // over Hh*Nn
    int h = idx >> 12;                          // / Nn
    const float* wr = g_Wh + (size_t)idx * O;
    const float* av = a + h * 2 * O;
    float f1 = 0.f, f2 = 0.f;
#pragma unroll
    for (int o = 0; o < O; o++) {
        float w = wr[o];
        f1 += w * av[o];
        f2 += w * av[O + o];
    }
    g_E1[idx] = make_float2(expf(f1), expf(0.2f * f1));
    g_E2[idx] = make_float2(expf(f2), expf(0.2f * f2));
}

// ---------------- fp16 tensor-core masked-softmax aggregation ----------------
// 32-row CTA tile (grid=512, 3-4 CTAs/SM), THREADS = 8*O, uniform warp layout
// NW_M=2 / WN=8. Double-buffered smem, ONE barrier per chunk. Weights piped
// through registers (E2 via float4 LDG, mask preloaded 4 chunks/LDG.128);
// Wh streamed via 16B cp.async from pre-converted g_Wh16.
template <int O>
__global__ __launch_bounds__(8 * O) void agg_mma_kernel(float* __restrict__ out,
                                                        int HO) {
    constexpr int THREADS = 8 * O;
    constexpr int NW_N = O / 8;                 // warp grid cols (NW_M = 2)
    constexpr int SWS = 40;                     // sW stride (halves), 80B rows
    constexpr int SBS = O + 8;                  // sWh stride (halves), 16B-mult
    constexpr int TPR = O / 4;                  // weight producers per row
    constexpr int KPT = 128 / O;                // k's per producer thread

    __shared__ __align__(16) __half sW[2][32][SWS];   // weights [row][k]
    __shared__ __align__(16) __half sWh[2][32][SBS];  // Wh chunk [k][o]
    __shared__ float sZq[THREADS];
    __shared__ float sZ[32];

    const int h = blockIdx.y;
    const int n0 = blockIdx.x * 32;
    const int t = threadIdx.x;
    const int lane = t & 31, wid = t >> 5;
    const int row0 = (wid / NW_N) * 16, col0 = (wid % NW_N) * 8;

    // weight-producer mapping: TPR threads per row, contiguous KPT-k segments
    const int rq = t / TPR, kq = t % TPR;
    const float2 e1 = g_E1[h * Nn + n0 + rq];
    const float2* E2H = g_E2 + h * Nn;
    const uint32_t* mrow = g_mask + (size_t)(n0 + rq) * NWORDS;

    // cp.async mapping: 4*O threads copy 16B each of the 32 x O half tile
    const bool cpa = (t < 4 * O);
    const int cjj = t / (O / 8), coh = (t % (O / 8)) * 8;
    const __half* whsrc = g_Wh16 + ((size_t)h * Nn + cjj) * O + coh;

    float acc[4] = {0.f, 0.f, 0.f, 0.f};
    float zloc = 0.f;

    uint32_t wreg[KPT / 2];
    uint32_t mbuf[4];

    auto produce_w = [&](int c) {
        if ((c & 3) == 0) {
            uint4 mv = *(const uint4*)(mrow + c);
            mbuf[0] = mv.x; mbuf[1] = mv.y; mbuf[2] = mv.z; mbuf[3] = mv.w;
        }
        const int j0 = c << 5;
        uint32_t m = mbuf[c & 3] >> (kq * KPT);
#pragma unroll
        for (int i = 0; i < KPT / 2; i++) {
            float4 e2 = *(const float4*)&E2H[j0 + kq * KPT + i * 2];
            float wa = ((m >> (i * 2)) & 1u) ? fmaxf(e1.x * e2.x, e1.y * e2.y) : 0.f;
            float wb = ((m >> (i * 2 + 1)) & 1u) ? fmaxf(e1.x * e2.z, e1.y * e2.w) : 0.f;
            __half2 hw = __floats2half2_rn(wa, wb);
            wreg[i] = *(uint32_t*)&hw;
        }
    };
    auto issue_wh = [&](int c, int buf) {
        if (cpa)
            cp_async16(smem_cast(&sWh[buf][cjj][coh]), whsrc + (size_t)(c << 5) * O);
        cp_commit();
    };

    produce_w(0);
    issue_wh(0, 0);

    for (int c = 0; c < NWORDS; c++) {
        const int buf = c & 1;
        // store weights(c), accumulate Z from fp16-rounded values
#pragma unroll
        for (int i = 0; i < KPT / 2; i++) {
            *(uint32_t*)&sW[buf][rq][kq * KPT + i * 2] = wreg[i];
            float2 f = __half22float2(*(__half2*)&wreg[i]);
            zloc += f.x + f.y;
        }
        cp_wait0();       // Wh(buf) copy landed
        __syncthreads();  // everyone's stores + copies visible
        if (c + 1 < NWORDS) {
            produce_w(c + 1);
            issue_wh(c + 1, buf ^ 1);
        }
        // consume chunk c from smem[buf]
        uint32_t a[2][4], bfr[4];
#pragma unroll
        for (int ks = 0; ks < 2; ks++)
            ldsm_x4(a[ks], smem_cast(&sW[buf][row0 + (lane & 15)]
                                        [ks * 16 + ((lane >> 4) & 1) * 8]));
        ldsm_x4t(bfr, smem_cast(&sWh[buf][lane][col0]));
#pragma unroll
        for (int ks = 0; ks < 2; ks++)
            asm volatile(
                "mma.sync.aligned.m16n8k16.row.col.f32.f16.f16.f32 "
                "{%0,%1,%2,%3}, {%4,%5,%6,%7}, {%8,%9}, {%0,%1,%2,%3};"
                : "+f"(acc[0]), "+f"(acc[1]), "+f"(acc[2]), "+f"(acc[3])
                : "r"(a[ks][0]), "r"(a[ks][1]), "r"(a[ks][2]), "r"(a[ks][3]),
                  "r"(bfr[2 * ks]), "r"(bfr[2 * ks + 1]));
    }
    // reduce Z per row (TPR producer threads per row)
    sZq[t] = zloc;
    __syncthreads();
    if (t < 32) {
        float z = 0.f;
#pragma unroll
        for (int i = 0; i < TPR; i++) z += sZq[t * TPR + i];
        sZ[t] = z;
    }
    __syncthreads();
    // epilogue: normalize, ELU, head-concat store
    {
        int r = row0 + (lane >> 2);
        float iz0 = 1.f / sZ[r];
        float iz1 = 1.f / sZ[r + 8];
        int cb = col0 + (lane & 3) * 2;
        float v0 = acc[0] * iz0;
        float v1 = acc[1] * iz0;
        float v2 = acc[2] * iz1;
        float v3 = acc[3] * iz1;
        v0 = v0 > 0.f ? v0 : expm1f(v0);
        v1 = v1 > 0.f ? v1 : expm1f(v1);
        v2 = v2 > 0.f ? v2 : expm1f(v2);
        v3 = v3 > 0.f ? v3 : expm1f(v3);
        *(float2*)&out[(size_t)(n0 + r) * HO + h * O + cb] = make_float2(v0, v1);
        *(float2*)&out[(size_t)(n0 + r + 8) * HO + h * O + cb] = make_float2(v2, v3);
    }
}

// ---------------- final linear + log_softmax ---------------------------------
__global__ void final_kernel(const float* __restrict__ Wlin,
                             const float* __restrict__ blin,
                             float* __restrict__ out) {
    int lane = threadIdx.x & 31;
    int n = (blockIdx.x * blockDim.x + threadIdx.x) >> 5;  // one warp per row
    const float* hr = g_h3 + (size_t)n * 64;
    float v1 = -INFINITY;
    float a0 = blin[lane];
    float a1v = (lane < 8) ? blin[lane + 32] : 0.f;
#pragma unroll 16
    for (int k = 0; k < 64; k++) {
        float hv = hr[k];
        a0 += hv * Wlin[k * 40 + lane];
        if (lane < 8) a1v += hv * Wlin[k * 40 + lane + 32];
    }
    float v0 = a0;
    if (lane < 8) v1 = a1v;
    float m = fmaxf(v0, v1);
#pragma unroll
    for (int off = 16; off; off >>= 1) m = fmaxf(m, __shfl_xor_sync(0xffffffffu, m, off));
    float e = expf(v0 - m) + ((lane < 8) ? expf(v1 - m) : 0.f);
#pragma unroll
    for (int off = 16; off; off >>= 1) e += __shfl_xor_sync(0xffffffffu, e, off);
    float lse = m + logf(e);
    out[(size_t)n * 40 + lane] = v0 - lse;
    if (lane < 8) out[(size_t)n * 40 + lane + 32] = v1 - lse;
}

// ---------------- launch -----------------------------------------------------
extern "C" void kernel_launch(void* const* d_in, const int* in_sizes, int n_in,
                              void* d_out, int out_size) {
    const float* x    = (const float*)d_in[0];
    const int*   adj  = (const int*)d_in[1];
    const float* W1   = (const float*)d_in[2];
    const float* a1   = (const float*)d_in[3];
    const float* W2   = (const float*)d_in[4];
    const float* a2   = (const float*)d_in[5];
    const float* W3   = (const float*)d_in[6];
    const float* a3   = (const float*)d_in[7];
    const float* Wlin = (const float*)d_in[8];
    const float* blin = (const float*)d_in[9];
    float* out = (float*)d_out;

    float *h1, *h2, *h3;
    cudaGetSymbolAddress((void**)&h1, g_h1);
    cudaGetSymbolAddress((void**)&h2, g_h2);
    cudaGetSymbolAddress((void**)&h3, g_h3);

    pack_mask_kernel<<<(Nn * NWORDS) / 256, 256>>>(adj);

    dim3 ggrid(Nn / 128, Hh);
    dim3 agrid(Nn / 32, Hh);

    // stage 1: Fin=512, O=64
    gemm_wh_kernel<512, 64, 8, 4><<<ggrid, 256>>>(x, W1);
    fe_kernel<64><<<(Hh * Nn) / 256, 256>>>(a1);
    agg_mma_kernel<64><<<agrid, 512>>>(h1, 256);

    // stage 2: Fin=256, O=32
    gemm_wh_kernel<256, 32, 4, 4><<<ggrid, 256>>>(h1, W2);
    fe_kernel<32><<<(Hh * Nn) / 256, 256>>>(a2);
    agg_mma_kernel<32><<<agrid, 256>>>(h2, 128);

    // stage 3: Fin=128, O=16
    gemm_wh_kernel<128, 16, 4, 2><<<ggrid, 256>>>(h2, W3);
    fe_kernel<16><<<(Hh * Nn) / 256, 256>>>(a3);
    agg_mma_kernel<16><<<agrid, 128>>>(h3, 64);

    final_kernel<<<(Nn * 32) / 256, 256>>>(Wlin, blin, out);
}

// round 10
// speedup vs baseline: 1.3517x; 1.3517x over previous
#include <cuda_runtime.h>
#include <cuda_fp16.h>
#include <math.h>
#include <stdint.h>

#define Nn 4096
#define Hh 4
#define NWORDS 128   // Nn/32

// ---------------- scratch (static device globals; no allocation) -------------
__device__ uint32_t g_mask[Nn * NWORDS];          // 2 MB packed adjacency
__device__ float g_Wh[Hh * Nn * 64];              // fp32 Wh (for fe_kernel)
__device__ __half g_Wh16[Hh * Nn * 64];           // fp16 Wh (for agg cp.async)
__device__ __half2 g_E1h[Hh * Nn];                // (e^f1, e^{0.2 f1}) fp16
__device__ __half2 g_E2h[Hh * Nn];                // (e^f2, e^{0.2 f2}) fp16
__device__ float g_h1[Nn * 256];
__device__ float g_h2[Nn * 128];
__device__ float g_h3[Nn * 64];

static __device__ __forceinline__ uint32_t smem_cast(const void* p) {
    return (uint32_t)__cvta_generic_to_shared(p);
}

static __device__ __forceinline__ void ldsm_x4(uint32_t* r, uint32_t addr) {
    asm volatile("ldmatrix.sync.aligned.m8n8.x4.shared.b16 {%0,%1,%2,%3}, [%4];"
                 : "=r"(r[0]), "=r"(r[1]), "=r"(r[2]), "=r"(r[3]) : "r"(addr));
}

static __device__ __forceinline__ void ldsm_x4t(uint32_t* r, uint32_t addr) {
    asm volatile("ldmatrix.sync.aligned.m8n8.x4.trans.shared.b16 {%0,%1,%2,%3}, [%4];"
                 : "=r"(r[0]), "=r"(r[1]), "=r"(r[2]), "=r"(r[3]) : "r"(addr));
}

static __device__ __forceinline__ void cp_async16(uint32_t dst, const void* src) {
    asm volatile("cp.async.ca.shared.global [%0], [%1], 16;" :: "r"(dst), "l"(src));
}
static __device__ __forceinline__ void cp_commit() {
    asm volatile("cp.async.commit_group;");
}
static __device__ __forceinline__ void cp_wait0() {
    asm volatile("cp.async.wait_group 0;");
}

// ---------------- pack adjacency into bitmask --------------------------------
__global__ void pack_mask_kernel(const int* __restrict__ adj) {
    int idx = blockIdx.x * blockDim.x + threadIdx.x;  // one thread per 32-bit word
    int i = idx >> 7;
    int w = idx & 127;
    const int4* p = reinterpret_cast<const int4*>(adj + (size_t)i * Nn + (w << 5));
    uint32_t m = 0u;
#pragma unroll
    for (int q = 0; q < 8; q++) {
        int4 v = p[q];
        if (v.x) m |= 1u << (q * 4 + 0);
        if (v.y) m |= 1u << (q * 4 + 1);
        if (v.z) m |= 1u << (q * 4 + 2);
        if (v.w) m |= 1u << (q * 4 + 3);
    }
    g_mask[idx] = m;
}

// ---------------- Wh = x @ W[h]  (per head); writes fp32 + fp16 --------------
template <int FIN, int O, int TM, int TN>
__global__ __launch_bounds__(256) void gemm_wh_kernel(const float* __restrict__ x,
                                                      const float* __restrict__ W) {
    const int h = blockIdx.y;
    const int n0 = blockIdx.x * 128;
    const int t = threadIdx.x;
    __shared__ float xs[32][132];  // [f][row], padded, 16B-aligned rows
    __shared__ float ws[32][O];    // [f][o]
    const int CG = O / TN;
    const int rg = t / CG, cg = t % CG;
    float acc[TM][TN];
#pragma unroll
    for (int k = 0; k < TM; k++)
#pragma unroll
        for (int u = 0; u < TN; u++) acc[k][u] = 0.f;
    const float* Wc = W + (size_t)h * FIN * O;
    for (int f0 = 0; f0 < FIN; f0 += 32) {
        __syncthreads();
#pragma unroll
        for (int k = 0; k < 16; k++) {
            int idx = t + k * 256;
            int f = idx & 31, row = idx >> 5;
            xs[f][row] = x[(size_t)(n0 + row) * FIN + f0 + f];
        }
#pragma unroll
        for (int k = 0; k < (32 * O) / 256; k++) {
            int idx = t + k * 256;
            int o = idx % O, f = idx / O;
            ws[f][o] = Wc[(size_t)(f0 + f) * O + o];
        }
        __syncthreads();
#pragma unroll 8
        for (int f = 0; f < 32; f++) {
            float xv[TM], wv[TN];
#pragma unroll
            for (int q = 0; q < TM / 4; q++)
                *(float4*)&xv[q * 4] = *(const float4*)&xs[f][rg * TM + q * 4];
            if (TN >= 4) {
#pragma unroll
                for (int q = 0; q < TN / 4; q++)
                    *(float4*)&wv[q * 4] = *(const float4*)&ws[f][cg * TN + q * 4];
            } else {
                *(float2*)&wv[0] = *(const float2*)&ws[f][cg * TN];
            }
#pragma unroll
            for (int k = 0; k < TM; k++)
#pragma unroll
                for (int u = 0; u < TN; u++) acc[k][u] += xv[k] * wv[u];
        }
    }
#pragma unroll
    for (int k = 0; k < TM; k++) {
        int n = n0 + rg * TM + k;
#pragma unroll
        for (int u = 0; u < TN; u++) {
            size_t idx = ((size_t)h * Nn + n) * O + cg * TN + u;
            g_Wh[idx] = acc[k][u];
            g_Wh16[idx] = __float2half(acc[k][u]);
        }
    }
}

// ---------------- per-node attention scalars ---------------------------------
template <int O>
__global__ void fe_kernel(const float* __restrict__ a) {
    int idx = blockIdx.x * 256 + threadIdx.x;  // over Hh*Nn
    int h = idx >> 12;                          // / Nn
    const float* wr = g_Wh + (size_t)idx * O;
    const float* av = a + h * 2 * O;
    float f1 = 0.f, f2 = 0.f;
#pragma unroll
    for (int o = 0; o < O; o++) {
        float w = wr[o];
        f1 += w * av[o];
        f2 += w * av[O + o];
    }
    g_E1h[idx] = __floats2half2_rn(expf(f1), expf(0.2f * f1));
    g_E2h[idx] = __floats2half2_rn(expf(f2), expf(0.2f * f2));
}

// ---------------- fp16 tensor-core masked-softmax aggregation ----------------
// w_ij = exp(leaky(f1_i+f2_j)) = max(e^f1*e^f2, e^{0.2f1}*e^{0.2f2}), computed
// in fp16 from packed half2 exp factors (1 LDG.128 per producer per chunk).
// 64-row CTA tile, double-buffered smem, ONE barrier per chunk; Wh streamed
// via 16B cp.async from pre-converted g_Wh16; fragments via ldmatrix.
template <int O, int THREADS>
__global__ __launch_bounds__(THREADS) void agg_mma_kernel(float* __restrict__ out,
                                                          int HO) {
    constexpr int NWARPS = THREADS / 32;
    constexpr int NW_N = NWARPS / 4;            // warp grid cols (NW_M = 4)
    constexpr int WN = O / NW_N;                // cols per warp
    constexpr int NT = WN / 8;                  // n8 tiles per warp
    constexpr int SWS = 40;                     // sW stride (halves), 80B rows
    constexpr int SBS = O + 8;                  // sWh stride (halves)
    constexpr int TPR = THREADS / 64;           // weight producers per row
    constexpr int KPT = 32 / TPR;               // j's per producer thread

    __shared__ __align__(16) __half sW[2][64][SWS];   // weights [row][k]
    __shared__ __align__(16) __half sWh[2][32][SBS];  // Wh chunk [k][o]
    __shared__ float sZq[THREADS];
    __shared__ float sZ[64];

    const int h = blockIdx.y;
    const int n0 = blockIdx.x * 64;
    const int t = threadIdx.x;
    const int lane = t & 31, wid = t >> 5;
    const int row0 = (wid / NW_N) * 16, col0 = (wid % NW_N) * WN;

    // weight-producer mapping: TPR threads per row, contiguous KPT-j segments
    const int rq = t / TPR, kq = t % TPR;
    const __half2 e1h = g_E1h[h * Nn + n0 + rq];
    const __half2* E2hH = g_E2h + h * Nn;
    const uint32_t* mrow = g_mask + (size_t)(n0 + rq) * NWORDS;

    // cp.async mapping: 4*O threads copy 16B each of the 32 x O half tile
    const bool cpa = (t < 4 * O);
    const int cjj = t / (O / 8), coh = (t % (O / 8)) * 8;
    const __half* whsrc = g_Wh16 + ((size_t)h * Nn + cjj) * O + coh;

    float acc[NT][4];
#pragma unroll
    for (int nt = 0; nt < NT; nt++)
#pragma unroll
        for (int q = 0; q < 4; q++) acc[nt][q] = 0.f;
    float zloc = 0.f;

    uint32_t wreg[KPT / 2];
    uint32_t mbuf[4];

    auto produce_w = [&](int c) {
        if ((c & 3) == 0) {
            uint4 mv = *(const uint4*)(mrow + c);
            mbuf[0] = mv.x; mbuf[1] = mv.y; mbuf[2] = mv.z; mbuf[3] = mv.w;
        }
        const int j0 = c << 5;
        uint32_t m = mbuf[c & 3] >> (kq * KPT);
        uint4 ebuf[KPT / 4];
#pragma unroll
        for (int v = 0; v < KPT / 4; v++)
            ebuf[v] = *(const uint4*)(E2hH + j0 + kq * KPT + v * 4);
        const __half2* e2arr = (const __half2*)ebuf;
#pragma unroll
        for (int i = 0; i < KPT / 2; i++) {
            __half2 pa = __hmul2(e1h, e2arr[2 * i]);
            __half2 pb = __hmul2(e1h, e2arr[2 * i + 1]);
            __half wa = __hmax(__low2half(pa), __high2half(pa));
            __half wb = __hmax(__low2half(pb), __high2half(pb));
            if (!((m >> (2 * i)) & 1u)) wa = __ushort_as_half(0);
            if (!((m >> (2 * i + 1)) & 1u)) wb = __ushort_as_half(0);
            __half2 hw = __halves2half2(wa, wb);
            wreg[i] = *(uint32_t*)&hw;
        }
    };
    auto issue_wh = [&](int c, int buf) {
        if (cpa)
            cp_async16(smem_cast(&sWh[buf][cjj][coh]), whsrc + (size_t)(c << 5) * O);
        cp_commit();
    };

    produce_w(0);
    issue_wh(0, 0);

    for (int c = 0; c < NWORDS; c++) {
        const int buf = c & 1;
        // store weights(c) (wide STS), accumulate Z from fp16-rounded values
        if (KPT == 4) {
            *(uint2*)&sW[buf][rq][kq * 4] = make_uint2(wreg[0], wreg[1]);
        } else {
            *(uint4*)&sW[buf][rq][kq * 8] =
                make_uint4(wreg[0], wreg[1], wreg[2], wreg[3]);
        }
#pragma unroll
        for (int i = 0; i < KPT / 2; i++) {
            float2 f = __half22float2(*(__half2*)&wreg[i]);
            zloc += f.x + f.y;
        }
        cp_wait0();       // Wh(buf) copy landed
        __syncthreads();  // everyone's stores + copies visible
        if (c + 1 < NWORDS) {
            produce_w(c + 1);
            issue_wh(c + 1, buf ^ 1);
        }
        // consume chunk c from smem[buf]
        uint32_t a[2][4], bfr[NT][4];
#pragma unroll
        for (int ks = 0; ks < 2; ks++)
            ldsm_x4(a[ks], smem_cast(&sW[buf][row0 + (lane & 15)]
                                        [ks * 16 + ((lane >> 4) & 1) * 8]));
#pragma unroll
        for (int nt = 0; nt < NT; nt++)
            ldsm_x4t(bfr[nt], smem_cast(&sWh[buf][lane][col0 + nt * 8]));
#pragma unroll
        for (int ks = 0; ks < 2; ks++)
#pragma unroll
            for (int nt = 0; nt < NT; nt++)
                asm volatile(
                    "mma.sync.aligned.m16n8k16.row.col.f32.f16.f16.f32 "
                    "{%0,%1,%2,%3}, {%4,%5,%6,%7}, {%8,%9}, {%0,%1,%2,%3};"
                    : "+f"(acc[nt][0]), "+f"(acc[nt][1]),
                      "+f"(acc[nt][2]), "+f"(acc[nt][3])
                    : "r"(a[ks][0]), "r"(a[ks][1]), "r"(a[ks][2]), "r"(a[ks][3]),
                      "r"(bfr[nt][2 * ks]), "r"(bfr[nt][2 * ks + 1]));
    }
    // reduce Z per row (TPR producer threads per row)
    sZq[t] = zloc;
    __syncthreads();
    if (t < 64) {
        float z = 0.f;
#pragma unroll
        for (int i = 0; i < TPR; i++) z += sZq[t * TPR + i];
        sZ[t] = z;
    }
    __syncthreads();
    // epilogue: normalize, ELU, head-concat store
    {
        int r = row0 + (lane >> 2);
        float iz0 = 1.f / sZ[r];
        float iz1 = 1.f / sZ[r + 8];
#pragma unroll
        for (int nt = 0; nt < NT; nt++) {
            int cb = col0 + nt * 8 + (lane & 3) * 2;
            float v0 = acc[nt][0] * iz0;
            float v1 = acc[nt][1] * iz0;
            float v2 = acc[nt][2] * iz1;
            float v3 = acc[nt][3] * iz1;
            v0 = v0 > 0.f ? v0 : expm1f(v0);
            v1 = v1 > 0.f ? v1 : expm1f(v1);
            v2 = v2 > 0.f ? v2 : expm1f(v2);
            v3 = v3 > 0.f ? v3 : expm1f(v3);
            *(float2*)&out[(size_t)(n0 + r) * HO + h * O + cb] = make_float2(v0, v1);
            *(float2*)&out[(size_t)(n0 + r + 8) * HO + h * O + cb] = make_float2(v2, v3);
        }
    }
}

// ---------------- final linear + log_softmax ---------------------------------
__global__ void final_kernel(const float* __restrict__ Wlin,
                             const float* __restrict__ blin,
                             float* __restrict__ out) {
    int lane = threadIdx.x & 31;
    int n = (blockIdx.x * blockDim.x + threadIdx.x) >> 5;  // one warp per row
    const float* hr = g_h3 + (size_t)n * 64;
    float v1 = -INFINITY;
    float a0 = blin[lane];
    float a1v = (lane < 8) ? blin[lane + 32] : 0.f;
#pragma unroll 16
    for (int k = 0; k < 64; k++) {
        float hv = hr[k];
        a0 += hv * Wlin[k * 40 + lane];
        if (lane < 8) a1v += hv * Wlin[k * 40 + lane + 32];
    }
    float v0 = a0;
    if (lane < 8) v1 = a1v;
    float m = fmaxf(v0, v1);
#pragma unroll
    for (int off = 16; off; off >>= 1) m = fmaxf(m, __shfl_xor_sync(0xffffffffu, m, off));
    float e = expf(v0 - m) + ((lane < 8) ? expf(v1 - m) : 0.f);
#pragma unroll
    for (int off = 16; off; off >>= 1) e += __shfl_xor_sync(0xffffffffu, e, off);
    float lse = m + logf(e);
    out[(size_t)n * 40 + lane] = v0 - lse;
    if (lane < 8) out[(size_t)n * 40 + lane + 32] = v1 - lse;
}

// ---------------- launch -----------------------------------------------------
extern "C" void kernel_launch(void* const* d_in, const int* in_sizes, int n_in,
                              void* d_out, int out_size) {
    const float* x    = (const float*)d_in[0];
    const int*   adj  = (const int*)d_in[1];
    const float* W1   = (const float*)d_in[2];
    const float* a1   = (const float*)d_in[3];
    const float* W2   = (const float*)d_in[4];
    const float* a2   = (const float*)d_in[5];
    const float* W3   = (const float*)d_in[6];
    const float* a3   = (const float*)d_in[7];
    const float* Wlin = (const float*)d_in[8];
    const float* blin = (const float*)d_in[9];
    float* out = (float*)d_out;

    float *h1, *h2, *h3;
    cudaGetSymbolAddress((void**)&h1, g_h1);
    cudaGetSymbolAddress((void**)&h2, g_h2);
    cudaGetSymbolAddress((void**)&h3, g_h3);

    pack_mask_kernel<<<(Nn * NWORDS) / 256, 256>>>(adj);

    dim3 ggrid(Nn / 128, Hh);
    dim3 agrid(Nn / 64, Hh);

    // stage 1: Fin=512, O=64
    gemm_wh_kernel<512, 64, 8, 4><<<ggrid, 256>>>(x, W1);
    fe_kernel<64><<<(Hh * Nn) / 256, 256>>>(a1);
    agg_mma_kernel<64, 512><<<agrid, 512>>>(h1, 256);

    // stage 2: Fin=256, O=32
    gemm_wh_kernel<256, 32, 4, 4><<<ggrid, 256>>>(h1, W2);
    fe_kernel<32><<<(Hh * Nn) / 256, 256>>>(a2);
    agg_mma_kernel<32, 256><<<agrid, 256>>>(h2, 128);

    // stage 3: Fin=128, O=16
    gemm_wh_kernel<128, 16, 4, 2><<<ggrid, 256>>>(h2, W3);
    fe_kernel<16><<<(Hh * Nn) / 256, 256>>>(a3);
    agg_mma_kernel<16, 256><<<agrid, 256>>>(h3, 64);

    final_kernel<<<(Nn * 32) / 256, 256>>>(Wlin, blin, out);
}

// round 11
// speedup vs baseline: 1.5037x; 1.1124x over previous
#include <cuda_runtime.h>
#include <cuda_fp16.h>
#include <math.h>
#include <stdint.h>

#define Nn 4096
#define Hh 4
#define NWORDS 128   // Nn/32

// ---------------- scratch (static device globals; no allocation) -------------
__device__ uint32_t g_mask[Nn * NWORDS];          // 2 MB packed adjacency
__device__ __half g_Wh16[Hh * Nn * 64];           // fp16 Wh (for agg cp.async)
__device__ __half2 g_E1h[Hh * Nn];                // (e^f1, e^{0.2 f1}) fp16
__device__ __half2 g_E2h[Hh * Nn];                // (e^f2, e^{0.2 f2}) fp16
__device__ float g_h1[Nn * 256];
__device__ float g_h2[Nn * 128];
__device__ float g_h3[Nn * 64];

static __device__ __forceinline__ uint32_t smem_cast(const void* p) {
    return (uint32_t)__cvta_generic_to_shared(p);
}

static __device__ __forceinline__ void ldsm_x4(uint32_t* r, uint32_t addr) {
    asm volatile("ldmatrix.sync.aligned.m8n8.x4.shared.b16 {%0,%1,%2,%3}, [%4];"
                 : "=r"(r[0]), "=r"(r[1]), "=r"(r[2]), "=r"(r[3]) : "r"(addr));
}

static __device__ __forceinline__ void ldsm_x4t(uint32_t* r, uint32_t addr) {
    asm volatile("ldmatrix.sync.aligned.m8n8.x4.trans.shared.b16 {%0,%1,%2,%3}, [%4];"
                 : "=r"(r[0]), "=r"(r[1]), "=r"(r[2]), "=r"(r[3]) : "r"(addr));
}

static __device__ __forceinline__ void cp_async16(uint32_t dst, const void* src) {
    asm volatile("cp.async.ca.shared.global [%0], [%1], 16;" :: "r"(dst), "l"(src));
}
static __device__ __forceinline__ void cp_commit() {
    asm volatile("cp.async.commit_group;");
}
static __device__ __forceinline__ void cp_wait0() {
    asm volatile("cp.async.wait_group 0;");
}

// ---------------- pack adjacency into bitmask --------------------------------
__global__ void pack_mask_kernel(const int* __restrict__ adj) {
    int idx = blockIdx.x * blockDim.x + threadIdx.x;  // one thread per 32-bit word
    int i = idx >> 7;
    int w = idx & 127;
    const int4* p = reinterpret_cast<const int4*>(adj + (size_t)i * Nn + (w << 5));
    uint32_t m = 0u;
#pragma unroll
    for (int q = 0; q < 8; q++) {
        int4 v = p[q];
        if (v.x) m |= 1u << (q * 4 + 0);
        if (v.y) m |= 1u << (q * 4 + 1);
        if (v.z) m |= 1u << (q * 4 + 2);
        if (v.w) m |= 1u << (q * 4 + 3);
    }
    g_mask[idx] = m;
}

// ------- Wh = x @ W[h] (per head) + fused attention scalars (fe) -------------
// After the GEMM, each CG-thread group holds a full Wh row; f1/f2 are reduced
// with shfl within the group and the exp factors written directly.
template <int FIN, int O, int TM, int TN>
__global__ __launch_bounds__(256) void gemm_wh_kernel(const float* __restrict__ x,
                                                      const float* __restrict__ W,
                                                      const float* __restrict__ a) {
    const int h = blockIdx.y;
    const int n0 = blockIdx.x * 128;
    const int t = threadIdx.x;
    __shared__ float xs[32][132];  // [f][row], padded, 16B-aligned rows
    __shared__ float ws[32][O];    // [f][o]
    constexpr int CG = O / TN;
    const int rg = t / CG, cg = t % CG;
    float acc[TM][TN];
#pragma unroll
    for (int k = 0; k < TM; k++)
#pragma unroll
        for (int u = 0; u < TN; u++) acc[k][u] = 0.f;
    const float* Wc = W + (size_t)h * FIN * O;
    for (int f0 = 0; f0 < FIN; f0 += 32) {
        __syncthreads();
#pragma unroll
        for (int k = 0; k < 16; k++) {
            int idx = t + k * 256;
            int f = idx & 31, row = idx >> 5;
            xs[f][row] = x[(size_t)(n0 + row) * FIN + f0 + f];
        }
#pragma unroll
        for (int k = 0; k < (32 * O) / 256; k++) {
            int idx = t + k * 256;
            int o = idx % O, f = idx / O;
            ws[f][o] = Wc[(size_t)(f0 + f) * O + o];
        }
        __syncthreads();
#pragma unroll 8
        for (int f = 0; f < 32; f++) {
            float xv[TM], wv[TN];
#pragma unroll
            for (int q = 0; q < TM / 4; q++)
                *(float4*)&xv[q * 4] = *(const float4*)&xs[f][rg * TM + q * 4];
            if (TN >= 4) {
#pragma unroll
                for (int q = 0; q < TN / 4; q++)
                    *(float4*)&wv[q * 4] = *(const float4*)&ws[f][cg * TN + q * 4];
            } else {
                *(float2*)&wv[0] = *(const float2*)&ws[f][cg * TN];
            }
#pragma unroll
            for (int k = 0; k < TM; k++)
#pragma unroll
                for (int u = 0; u < TN; u++) acc[k][u] += xv[k] * wv[u];
        }
    }
    // store fp16 Wh
#pragma unroll
    for (int k = 0; k < TM; k++) {
        int n = n0 + rg * TM + k;
#pragma unroll
        for (int u = 0; u < TN; u++)
            g_Wh16[((size_t)h * Nn + n) * O + cg * TN + u] = __float2half(acc[k][u]);
    }
    // fused fe: f1 = Wh.a[:O], f2 = Wh.a[O:]
    float av1[TN], av2[TN];
    const float* av = a + h * 2 * O;
#pragma unroll
    for (int u = 0; u < TN; u++) {
        av1[u] = av[cg * TN + u];
        av2[u] = av[O + cg * TN + u];
    }
#pragma unroll
    for (int k = 0; k < TM; k++) {
        float f1 = 0.f, f2 = 0.f;
#pragma unroll
        for (int u = 0; u < TN; u++) {
            f1 += acc[k][u] * av1[u];
            f2 += acc[k][u] * av2[u];
        }
#pragma unroll
        for (int off = CG / 2; off; off >>= 1) {
            f1 += __shfl_down_sync(0xffffffffu, f1, off, CG);
            f2 += __shfl_down_sync(0xffffffffu, f2, off, CG);
        }
        if (cg == 0) {
            int idx = h * Nn + n0 + rg * TM + k;
            g_E1h[idx] = __floats2half2_rn(expf(f1), expf(0.2f * f1));
            g_E2h[idx] = __floats2half2_rn(expf(f2), expf(0.2f * f2));
        }
    }
}

// ---------------- fp16 tensor-core masked-softmax aggregation ----------------
// 64-row CTA tile, JJ=64 j-chunks, double-buffered smem, ONE barrier/chunk.
// Weights computed fp16 from packed half2 exp factors; Wh streamed via 16B
// cp.async from pre-converted g_Wh16; fragments via ldmatrix.
template <int O, int THREADS>
__global__ __launch_bounds__(THREADS) void agg_mma_kernel(float* __restrict__ out,
                                                          int HO) {
    constexpr int JJ = 64;                      // j's per chunk
    constexpr int NCH = Nn / JJ;                // 64 chunks
    constexpr int NWARPS = THREADS / 32;
    constexpr int NW_N = NWARPS / 4;            // warp grid cols (NW_M = 4)
    constexpr int WN = O / NW_N;                // cols per warp
    constexpr int NT = WN / 8;                  // n8 tiles per warp
    constexpr int SWS = JJ + 8;                 // sW stride (halves), 144B rows
    constexpr int SBS = O + 8;                  // sWh stride (halves)
    constexpr int TPR = THREADS / 64;           // weight producers per row
    constexpr int KPT = JJ / TPR;               // j's per producer thread
    constexpr int NCP = JJ * O / 8;             // cp.async participant threads

    __shared__ __align__(16) __half sW[2][64][SWS];   // weights [row][k]
    __shared__ __align__(16) __half sWh[2][JJ][SBS];  // Wh chunk [k][o]
    __shared__ float sZq[THREADS];
    __shared__ float sZ[64];

    const int h = blockIdx.y;
    const int n0 = blockIdx.x * 64;
    const int t = threadIdx.x;
    const int lane = t & 31, wid = t >> 5;
    const int row0 = (wid / NW_N) * 16, col0 = (wid % NW_N) * WN;

    // weight-producer mapping: TPR threads per row, contiguous KPT-j segments
    const int rq = t / TPR, kq = t % TPR;
    const __half2 e1h = g_E1h[h * Nn + n0 + rq];
    const __half2* E2hH = g_E2h + h * Nn;
    const uint32_t* mrow = g_mask + (size_t)(n0 + rq) * NWORDS;

    // cp.async mapping: NCP threads copy 16B each of the JJ x O half tile
    const bool cpa = (t < NCP);
    const int cjj = t / (O / 8), coh = (t % (O / 8)) * 8;
    const __half* whsrc = g_Wh16 + ((size_t)h * Nn + cjj) * O + coh;

    float acc[NT][4];
#pragma unroll
    for (int nt = 0; nt < NT; nt++)
#pragma unroll
        for (int q = 0; q < 4; q++) acc[nt][q] = 0.f;
    float zloc = 0.f;

    uint32_t wreg[KPT / 2];
    uint32_t mbuf[4];

    auto produce_w = [&](int c) {
        if ((c & 1) == 0) {  // 4 mask words = 2 chunks per LDG.128
            uint4 mv = *(const uint4*)(mrow + 2 * c);
            mbuf[0] = mv.x; mbuf[1] = mv.y; mbuf[2] = mv.z; mbuf[3] = mv.w;
        }
        uint64_t m64 = ((uint64_t)mbuf[(c & 1) * 2 + 1] << 32) | mbuf[(c & 1) * 2];
        uint32_t m = (uint32_t)(m64 >> (kq * KPT));
        const int j0 = c * JJ + kq * KPT;
        uint4 ebuf[KPT / 4];
#pragma unroll
        for (int v = 0; v < KPT / 4; v++)
            ebuf[v] = *(const uint4*)(E2hH + j0 + v * 4);
        const __half2* e2arr = (const __half2*)ebuf;
#pragma unroll
        for (int i = 0; i < KPT / 2; i++) {
            __half2 pa = __hmul2(e1h, e2arr[2 * i]);
            __half2 pb = __hmul2(e1h, e2arr[2 * i + 1]);
            __half wa = __hmax(__low2half(pa), __high2half(pa));
            __half wb = __hmax(__low2half(pb), __high2half(pb));
            if (!((m >> (2 * i)) & 1u)) wa = __ushort_as_half(0);
            if (!((m >> (2 * i + 1)) & 1u)) wb = __ushort_as_half(0);
            __half2 hw = __halves2half2(wa, wb);
            wreg[i] = *(uint32_t*)&hw;
        }
    };
    auto issue_wh = [&](int c, int buf) {
        if (cpa)
            cp_async16(smem_cast(&sWh[buf][cjj][coh]),
                       whsrc + (size_t)(c * JJ) * O);
        cp_commit();
    };

    produce_w(0);
    issue_wh(0, 0);

    for (int c = 0; c < NCH; c++) {
        const int buf = c & 1;
        // store weights(c) (STS.128), accumulate Z from fp16-rounded values
#pragma unroll
        for (int s = 0; s < KPT / 8; s++)
            *(uint4*)&sW[buf][rq][kq * KPT + s * 8] =
                make_uint4(wreg[s * 4], wreg[s * 4 + 1],
                           wreg[s * 4 + 2], wreg[s * 4 + 3]);
#pragma unroll
        for (int i = 0; i < KPT / 2; i++) {
            float2 f = __half22float2(*(__half2*)&wreg[i]);
            zloc += f.x + f.y;
        }
        cp_wait0();       // Wh(buf) copy landed
        __syncthreads();  // everyone's stores + copies visible
        if (c + 1 < NCH) {
            produce_w(c + 1);
            issue_wh(c + 1, buf ^ 1);
        }
        // consume chunk c from smem[buf]: 4 k-steps of 16
        uint32_t a[4][4], bfr[NT][8];
#pragma unroll
        for (int ks = 0; ks < 4; ks++)
            ldsm_x4(a[ks], smem_cast(&sW[buf][row0 + (lane & 15)]
                                        [ks * 16 + ((lane >> 4) & 1) * 8]));
#pragma unroll
        for (int nt = 0; nt < NT; nt++) {
            ldsm_x4t(bfr[nt], smem_cast(&sWh[buf][lane][col0 + nt * 8]));
            ldsm_x4t(bfr[nt] + 4, smem_cast(&sWh[buf][32 + lane][col0 + nt * 8]));
        }
#pragma unroll
        for (int ks = 0; ks < 4; ks++)
#pragma unroll
            for (int nt = 0; nt < NT; nt++)
                asm volatile(
                    "mma.sync.aligned.m16n8k16.row.col.f32.f16.f16.f32 "
                    "{%0,%1,%2,%3}, {%4,%5,%6,%7}, {%8,%9}, {%0,%1,%2,%3};"
                    : "+f"(acc[nt][0]), "+f"(acc[nt][1]),
                      "+f"(acc[nt][2]), "+f"(acc[nt][3])
                    : "r"(a[ks][0]), "r"(a[ks][1]), "r"(a[ks][2]), "r"(a[ks][3]),
                      "r"(bfr[nt][2 * ks]), "r"(bfr[nt][2 * ks + 1]));
    }
    // reduce Z per row (TPR producer threads per row)
    sZq[t] = zloc;
    __syncthreads();
    if (t < 64) {
        float z = 0.f;
#pragma unroll
        for (int i = 0; i < TPR; i++) z += sZq[t * TPR + i];
        sZ[t] = z;
    }
    __syncthreads();
    // epilogue: normalize, ELU, head-concat store
    {
        int r = row0 + (lane >> 2);
        float iz0 = 1.f / sZ[r];
        float iz1 = 1.f / sZ[r + 8];
#pragma unroll
        for (int nt = 0; nt < NT; nt++) {
            int cb = col0 + nt * 8 + (lane & 3) * 2;
            float v0 = acc[nt][0] * iz0;
            float v1 = acc[nt][1] * iz0;
            float v2 = acc[nt][2] * iz1;
            float v3 = acc[nt][3] * iz1;
            v0 = v0 > 0.f ? v0 : expm1f(v0);
            v1 = v1 > 0.f ? v1 : expm1f(v1);
            v2 = v2 > 0.f ? v2 : expm1f(v2);
            v3 = v3 > 0.f ? v3 : expm1f(v3);
            *(float2*)&out[(size_t)(n0 + r) * HO + h * O + cb] = make_float2(v0, v1);
            *(float2*)&out[(size_t)(n0 + r + 8) * HO + h * O + cb] = make_float2(v2, v3);
        }
    }
}

// ---------------- final linear + log_softmax ---------------------------------
__global__ void final_kernel(const float* __restrict__ Wlin,
                             const float* __restrict__ blin,
                             float* __restrict__ out) {
    int lane = threadIdx.x & 31;
    int n = (blockIdx.x * blockDim.x + threadIdx.x) >> 5;  // one warp per row
    const float* hr = g_h3 + (size_t)n * 64;
    float v1 = -INFINITY;
    float a0 = blin[lane];
    float a1v = (lane < 8) ? blin[lane + 32] : 0.f;
#pragma unroll 16
    for (int k = 0; k < 64; k++) {
        float hv = hr[k];
        a0 += hv * Wlin[k * 40 + lane];
        if (lane < 8) a1v += hv * Wlin[k * 40 + lane + 32];
    }
    float v0 = a0;
    if (lane < 8) v1 = a1v;
    float m = fmaxf(v0, v1);
#pragma unroll
    for (int off = 16; off; off >>= 1) m = fmaxf(m, __shfl_xor_sync(0xffffffffu, m, off));
    float e = expf(v0 - m) + ((lane < 8) ? expf(v1 - m) : 0.f);
#pragma unroll
    for (int off = 16; off; off >>= 1) e += __shfl_xor_sync(0xffffffffu, e, off);
    float lse = m + logf(e);
    out[(size_t)n * 40 + lane] = v0 - lse;
    if (lane < 8) out[(size_t)n * 40 + lane + 32] = v1 - lse;
}

// ---------------- launch -----------------------------------------------------
extern "C" void kernel_launch(void* const* d_in, const int* in_sizes, int n_in,
                              void* d_out, int out_size) {
    const float* x    = (const float*)d_in[0];
    const int*   adj  = (const int*)d_in[1];
    const float* W1   = (const float*)d_in[2];
    const float* a1   = (const float*)d_in[3];
    const float* W2   = (const float*)d_in[4];
    const float* a2   = (const float*)d_in[5];
    const float* W3   = (const float*)d_in[6];
    const float* a3   = (const float*)d_in[7];
    const float* Wlin = (const float*)d_in[8];
    const float* blin = (const float*)d_in[9];
    float* out = (float*)d_out;

    float *h1, *h2, *h3;
    cudaGetSymbolAddress((void**)&h1, g_h1);
    cudaGetSymbolAddress((void**)&h2, g_h2);
    cudaGetSymbolAddress((void**)&h3, g_h3);

    pack_mask_kernel<<<(Nn * NWORDS) / 256, 256>>>(adj);

    dim3 ggrid(Nn / 128, Hh);
    dim3 agrid(Nn / 64, Hh);

    // stage 1: Fin=512, O=64
    gemm_wh_kernel<512, 64, 8, 4><<<ggrid, 256>>>(x, W1, a1);
    agg_mma_kernel<64, 512><<<agrid, 512>>>(h1, 256);

    // stage 2: Fin=256, O=32
    gemm_wh_kernel<256, 32, 4, 4><<<ggrid, 256>>>(h1, W2, a2);
    agg_mma_kernel<32, 512><<<agrid, 512>>>(h2, 128);

    // stage 3: Fin=128, O=16
    gemm_wh_kernel<128, 16, 4, 2><<<ggrid, 256>>>(h2, W3, a3);
    agg_mma_kernel<16, 256><<<agrid, 256>>>(h3, 64);

    final_kernel<<<(Nn * 32) / 256, 256>>>(Wlin, blin, out);
}

// round 12
// speedup vs baseline: 1.8282x; 1.2158x over previous
#include <cuda_runtime.h>
#include <cuda_fp16.h>
#include <math.h>
#include <stdint.h>

#define Nn 4096
#define Hh 4
#define NWORDS 128   // Nn/32

// ---------------- scratch (static device globals; no allocation) -------------
__device__ uint32_t g_mask[Nn * NWORDS];          // 2 MB packed adjacency
__device__ __half g_x16[Nn * 512];                // fp16 input features
__device__ __half g_W16[172032];                  // fp16 W1|W2|W3 (offsets below)
__device__ __half g_Wh16[Hh * Nn * 64];           // fp16 Wh
__device__ __half2 g_E1h[Hh * Nn];                // (e^f1, e^{0.2 f1}) fp16
__device__ __half2 g_E2h[Hh * Nn];                // (e^f2, e^{0.2 f2}) fp16
__device__ __half g_h1h[Nn * 256];
__device__ __half g_h2h[Nn * 128];
__device__ __half g_h3h[Nn * 64];

#define W2_OFF 131072   // 4*512*64
#define W3_OFF 163840   // +4*256*32

static __device__ __forceinline__ uint32_t smem_cast(const void* p) {
    return (uint32_t)__cvta_generic_to_shared(p);
}

static __device__ __forceinline__ void ldsm_x4(uint32_t* r, uint32_t addr) {
    asm volatile("ldmatrix.sync.aligned.m8n8.x4.shared.b16 {%0,%1,%2,%3}, [%4];"
                 : "=r"(r[0]), "=r"(r[1]), "=r"(r[2]), "=r"(r[3]) : "r"(addr));
}

static __device__ __forceinline__ void ldsm_x4t(uint32_t* r, uint32_t addr) {
    asm volatile("ldmatrix.sync.aligned.m8n8.x4.trans.shared.b16 {%0,%1,%2,%3}, [%4];"
                 : "=r"(r[0]), "=r"(r[1]), "=r"(r[2]), "=r"(r[3]) : "r"(addr));
}

static __device__ __forceinline__ void cp_async16(uint32_t dst, const void* src) {
    asm volatile("cp.async.ca.shared.global [%0], [%1], 16;" :: "r"(dst), "l"(src));
}
static __device__ __forceinline__ void cp_commit() {
    asm volatile("cp.async.commit_group;");
}
static __device__ __forceinline__ void cp_wait0() {
    asm volatile("cp.async.wait_group 0;");
}

static __device__ __forceinline__ void mma_16816(float* acc, const uint32_t* a,
                                                 uint32_t b0, uint32_t b1) {
    asm volatile(
        "mma.sync.aligned.m16n8k16.row.col.f32.f16.f16.f32 "
        "{%0,%1,%2,%3}, {%4,%5,%6,%7}, {%8,%9}, {%0,%1,%2,%3};"
        : "+f"(acc[0]), "+f"(acc[1]), "+f"(acc[2]), "+f"(acc[3])
        : "r"(a[0]), "r"(a[1]), "r"(a[2]), "r"(a[3]), "r"(b0), "r"(b1));
}

// ---------------- pack adjacency into bitmask --------------------------------
__global__ void pack_mask_kernel(const int* __restrict__ adj) {
    int idx = blockIdx.x * blockDim.x + threadIdx.x;  // one thread per 32-bit word
    int i = idx >> 7;
    int w = idx & 127;
    const int4* p = reinterpret_cast<const int4*>(adj + (size_t)i * Nn + (w << 5));
    uint32_t m = 0u;
#pragma unroll
    for (int q = 0; q < 8; q++) {
        int4 v = p[q];
        if (v.x) m |= 1u << (q * 4 + 0);
        if (v.y) m |= 1u << (q * 4 + 1);
        if (v.z) m |= 1u << (q * 4 + 2);
        if (v.w) m |= 1u << (q * 4 + 3);
    }
    g_mask[idx] = m;
}

// ---------------- fp32 -> fp16 convert ----------------------------------------
__global__ void f2h_kernel(const float* __restrict__ src, __half* __restrict__ dst,
                           int n4) {
    int i = blockIdx.x * 256 + threadIdx.x;
    if (i < n4) {
        float4 v = ((const float4*)src)[i];
        __half2 a = __floats2half2_rn(v.x, v.y);
        __half2 b = __floats2half2_rn(v.z, v.w);
        ((uint2*)dst)[i] = make_uint2(*(uint32_t*)&a, *(uint32_t*)&b);
    }
}

// ------- tensor-core Wh = A @ W[h] + fused attention scalars (fe) ------------
// 64-row CTA tile, K chunks of 64, double-buffered cp.async, m16n8k16 fp16 MMA
// with fp32 accumulate. Epilogue stores fp16 Wh and reduces f1/f2 -> exp factors.
template <int FIN, int O, int THREADS>
__global__ __launch_bounds__(THREADS) void gemm_mma_kernel(
    const __half* __restrict__ A,     // [Nn][FIN]
    const __half* __restrict__ Wb,    // [Hh][FIN][O] fp16
    const float* __restrict__ a) {    // [Hh][2*O]
    constexpr int KC = 64;
    constexpr int NCH = FIN / KC;
    constexpr int NWARPS = THREADS / 32;
    constexpr int NW_N = NWARPS / 4;            // warp grid: 4 rows x NW_N cols
    constexpr int WN = O / NW_N;
    constexpr int NT = WN / 8;
    constexpr int SAS = KC + 8;
    constexpr int SBS = O + 8;
    constexpr int ASEG = 64 * KC / 8;           // 512
    constexpr int BSEG = KC * O / 8;

    __shared__ __align__(16) __half sA[2][64][SAS];
    __shared__ __align__(16) __half sB[2][KC][SBS];
    __shared__ float sF1[64][NW_N], sF2[64][NW_N];

    const int h = blockIdx.y;
    const int n0 = blockIdx.x * 64;
    const int t = threadIdx.x;
    const int lane = t & 31, wid = t >> 5;
    const int row0 = (wid / NW_N) * 16, col0 = (wid % NW_N) * WN;
    const int wn = wid % NW_N;

    const __half* Abase = A + (size_t)n0 * FIN;
    const __half* Bbase = Wb + (size_t)h * FIN * O;

    float acc[NT][4];
#pragma unroll
    for (int nt = 0; nt < NT; nt++)
#pragma unroll
        for (int q = 0; q < 4; q++) acc[nt][q] = 0.f;

    auto issue = [&](int c, int buf) {
#pragma unroll
        for (int v = 0; v < (ASEG + THREADS - 1) / THREADS; v++) {
            int i = t + v * THREADS;
            if (i < ASEG) {
                int row = i >> 3, off = (i & 7) * 8;
                cp_async16(smem_cast(&sA[buf][row][off]),
                           Abase + (size_t)row * FIN + c * KC + off);
            }
        }
#pragma unroll
        for (int v = 0; v < (BSEG + THREADS - 1) / THREADS; v++) {
            int i = t + v * THREADS;
            if (i < BSEG) {
                int kr = i / (O / 8), off = (i % (O / 8)) * 8;
                cp_async16(smem_cast(&sB[buf][kr][off]),
                           Bbase + (size_t)(c * KC + kr) * O + off);
            }
        }
        cp_commit();
    };

    issue(0, 0);
    for (int c = 0; c < NCH; c++) {
        const int buf = c & 1;
        cp_wait0();
        __syncthreads();
        if (c + 1 < NCH) issue(c + 1, buf ^ 1);
        uint32_t av[4][4], bfr[NT][8];
#pragma unroll
        for (int ks = 0; ks < 4; ks++)
            ldsm_x4(av[ks], smem_cast(&sA[buf][row0 + (lane & 15)]
                                         [ks * 16 + ((lane >> 4) & 1) * 8]));
#pragma unroll
        for (int nt = 0; nt < NT; nt++) {
            ldsm_x4t(bfr[nt], smem_cast(&sB[buf][lane][col0 + nt * 8]));
            ldsm_x4t(bfr[nt] + 4, smem_cast(&sB[buf][32 + lane][col0 + nt * 8]));
        }
#pragma unroll
        for (int ks = 0; ks < 4; ks++)
#pragma unroll
            for (int nt = 0; nt < NT; nt++)
                mma_16816(acc[nt], av[ks], bfr[nt][2 * ks], bfr[nt][2 * ks + 1]);
        __syncthreads();  // consume done before next issue overwrites other buf
    }

    // epilogue: store fp16 Wh + fused fe
    const float* avec = a + h * 2 * O;
    const int r = row0 + (lane >> 2);
    float f1a = 0.f, f2a = 0.f, f1b = 0.f, f2b = 0.f;
#pragma unroll
    for (int nt = 0; nt < NT; nt++) {
        int cb = col0 + nt * 8 + (lane & 3) * 2;
        __half2 lo = __floats2half2_rn(acc[nt][0], acc[nt][1]);
        __half2 hi = __floats2half2_rn(acc[nt][2], acc[nt][3]);
        *(__half2*)&g_Wh16[((size_t)h * Nn + n0 + r) * O + cb] = lo;
        *(__half2*)&g_Wh16[((size_t)h * Nn + n0 + r + 8) * O + cb] = hi;
        float a10 = avec[cb], a11 = avec[cb + 1];
        float a20 = avec[O + cb], a21 = avec[O + cb + 1];
        f1a += acc[nt][0] * a10 + acc[nt][1] * a11;
        f2a += acc[nt][0] * a20 + acc[nt][1] * a21;
        f1b += acc[nt][2] * a10 + acc[nt][3] * a11;
        f2b += acc[nt][2] * a20 + acc[nt][3] * a21;
    }
#pragma unroll
    for (int off = 1; off <= 2; off <<= 1) {
        f1a += __shfl_xor_sync(0xffffffffu, f1a, off);
        f2a += __shfl_xor_sync(0xffffffffu, f2a, off);
        f1b += __shfl_xor_sync(0xffffffffu, f1b, off);
        f2b += __shfl_xor_sync(0xffffffffu, f2b, off);
    }
    if ((lane & 3) == 0) {
        sF1[r][wn] = f1a; sF2[r][wn] = f2a;
        sF1[r + 8][wn] = f1b; sF2[r + 8][wn] = f2b;
    }
    __syncthreads();
    if (t < 64) {
        float f1 = 0.f, f2 = 0.f;
#pragma unroll
        for (int i = 0; i < NW_N; i++) { f1 += sF1[t][i]; f2 += sF2[t][i]; }
        int idx = h * Nn + n0 + t;
        g_E1h[idx] = __floats2half2_rn(expf(f1), expf(0.2f * f1));
        g_E2h[idx] = __floats2half2_rn(expf(f2), expf(0.2f * f2));
    }
}

// ---------------- fp16 tensor-core masked-softmax aggregation ----------------
// 64-row CTA tile, JJ=64 j-chunks, double-buffered smem, ONE barrier/chunk.
template <int O, int THREADS>
__global__ __launch_bounds__(THREADS) void agg_mma_kernel(__half* __restrict__ out,
                                                          int HO) {
    constexpr int JJ = 64;
    constexpr int NCH = Nn / JJ;
    constexpr int NWARPS = THREADS / 32;
    constexpr int NW_N = NWARPS / 4;
    constexpr int WN = O / NW_N;
    constexpr int NT = WN / 8;
    constexpr int SWS = JJ + 8;
    constexpr int SBS = O + 8;
    constexpr int TPR = THREADS / 64;
    constexpr int KPT = JJ / TPR;
    constexpr int NCP = JJ * O / 8;

    __shared__ __align__(16) __half sW[2][64][SWS];
    __shared__ __align__(16) __half sWh[2][JJ][SBS];
    __shared__ float sZq[THREADS];
    __shared__ float sZ[64];

    const int h = blockIdx.y;
    const int n0 = blockIdx.x * 64;
    const int t = threadIdx.x;
    const int lane = t & 31, wid = t >> 5;
    const int row0 = (wid / NW_N) * 16, col0 = (wid % NW_N) * WN;

    const int rq = t / TPR, kq = t % TPR;
    const __half2 e1h = g_E1h[h * Nn + n0 + rq];
    const __half2* E2hH = g_E2h + h * Nn;
    const uint32_t* mrow = g_mask + (size_t)(n0 + rq) * NWORDS;

    const bool cpa = (t < NCP);
    const int cjj = t / (O / 8), coh = (t % (O / 8)) * 8;
    const __half* whsrc = g_Wh16 + ((size_t)h * Nn + cjj) * O + coh;

    float acc[NT][4];
#pragma unroll
    for (int nt = 0; nt < NT; nt++)
#pragma unroll
        for (int q = 0; q < 4; q++) acc[nt][q] = 0.f;
    float zloc = 0.f;

    uint32_t wreg[KPT / 2];
    uint32_t mbuf[4];

    auto produce_w = [&](int c) {
        if ((c & 1) == 0) {
            uint4 mv = *(const uint4*)(mrow + 2 * c);
            mbuf[0] = mv.x; mbuf[1] = mv.y; mbuf[2] = mv.z; mbuf[3] = mv.w;
        }
        uint64_t m64 = ((uint64_t)mbuf[(c & 1) * 2 + 1] << 32) | mbuf[(c & 1) * 2];
        uint32_t m = (uint32_t)(m64 >> (kq * KPT));
        const int j0 = c * JJ + kq * KPT;
        uint4 ebuf[KPT / 4];
#pragma unroll
        for (int v = 0; v < KPT / 4; v++)
            ebuf[v] = *(const uint4*)(E2hH + j0 + v * 4);
        const __half2* e2arr = (const __half2*)ebuf;
#pragma unroll
        for (int i = 0; i < KPT / 2; i++) {
            __half2 pa = __hmul2(e1h, e2arr[2 * i]);
            __half2 pb = __hmul2(e1h, e2arr[2 * i + 1]);
            __half wa = __hmax(__low2half(pa), __high2half(pa));
            __half wb = __hmax(__low2half(pb), __high2half(pb));
            if (!((m >> (2 * i)) & 1u)) wa = __ushort_as_half(0);
            if (!((m >> (2 * i + 1)) & 1u)) wb = __ushort_as_half(0);
            __half2 hw = __halves2half2(wa, wb);
            wreg[i] = *(uint32_t*)&hw;
        }
    };
    auto issue_wh = [&](int c, int buf) {
        if (cpa)
            cp_async16(smem_cast(&sWh[buf][cjj][coh]),
                       whsrc + (size_t)(c * JJ) * O);
        cp_commit();
    };

    produce_w(0);
    issue_wh(0, 0);

    for (int c = 0; c < NCH; c++) {
        const int buf = c & 1;
#pragma unroll
        for (int s = 0; s < KPT / 8; s++)
            *(uint4*)&sW[buf][rq][kq * KPT + s * 8] =
                make_uint4(wreg[s * 4], wreg[s * 4 + 1],
                           wreg[s * 4 + 2], wreg[s * 4 + 3]);
#pragma unroll
        for (int i = 0; i < KPT / 2; i++) {
            float2 f = __half22float2(*(__half2*)&wreg[i]);
            zloc += f.x + f.y;
        }
        cp_wait0();
        __syncthreads();
        if (c + 1 < NCH) {
            produce_w(c + 1);
            issue_wh(c + 1, buf ^ 1);
        }
        uint32_t a[4][4], bfr[NT][8];
#pragma unroll
        for (int ks = 0; ks < 4; ks++)
            ldsm_x4(a[ks], smem_cast(&sW[buf][row0 + (lane & 15)]
                                        [ks * 16 + ((lane >> 4) & 1) * 8]));
#pragma unroll
        for (int nt = 0; nt < NT; nt++) {
            ldsm_x4t(bfr[nt], smem_cast(&sWh[buf][lane][col0 + nt * 8]));
            ldsm_x4t(bfr[nt] + 4, smem_cast(&sWh[buf][32 + lane][col0 + nt * 8]));
        }
#pragma unroll
        for (int ks = 0; ks < 4; ks++)
#pragma unroll
            for (int nt = 0; nt < NT; nt++)
                mma_16816(acc[nt], a[ks], bfr[nt][2 * ks], bfr[nt][2 * ks + 1]);
    }
    sZq[t] = zloc;
    __syncthreads();
    if (t < 64) {
        float z = 0.f;
#pragma unroll
        for (int i = 0; i < TPR; i++) z += sZq[t * TPR + i];
        sZ[t] = z;
    }
    __syncthreads();
    {
        int r = row0 + (lane >> 2);
        float iz0 = 1.f / sZ[r];
        float iz1 = 1.f / sZ[r + 8];
#pragma unroll
        for (int nt = 0; nt < NT; nt++) {
            int cb = col0 + nt * 8 + (lane & 3) * 2;
            float v0 = acc[nt][0] * iz0;
            float v1 = acc[nt][1] * iz0;
            float v2 = acc[nt][2] * iz1;
            float v3 = acc[nt][3] * iz1;
            v0 = v0 > 0.f ? v0 : expm1f(v0);
            v1 = v1 > 0.f ? v1 : expm1f(v1);
            v2 = v2 > 0.f ? v2 : expm1f(v2);
            v3 = v3 > 0.f ? v3 : expm1f(v3);
            __half2 lo = __floats2half2_rn(v0, v1);
            __half2 hi = __floats2half2_rn(v2, v3);
            *(__half2*)&out[(size_t)(n0 + r) * HO + h * O + cb] = lo;
            *(__half2*)&out[(size_t)(n0 + r + 8) * HO + h * O + cb] = hi;
        }
    }
}

// ---------------- final linear + log_softmax ---------------------------------
__global__ void final_kernel(const float* __restrict__ Wlin,
                             const float* __restrict__ blin,
                             float* __restrict__ out) {
    int lane = threadIdx.x & 31;
    int n = (blockIdx.x * blockDim.x + threadIdx.x) >> 5;  // one warp per row
    const __half* hr = g_h3h + (size_t)n * 64;
    float v1 = -INFINITY;
    float a0 = blin[lane];
    float a1v = (lane < 8) ? blin[lane + 32] : 0.f;
#pragma unroll 16
    for (int k = 0; k < 64; k++) {
        float hv = __half2float(hr[k]);
        a0 += hv * Wlin[k * 40 + lane];
        if (lane < 8) a1v += hv * Wlin[k * 40 + lane + 32];
    }
    float v0 = a0;
    if (lane < 8) v1 = a1v;
    float m = fmaxf(v0, v1);
#pragma unroll
    for (int off = 16; off; off >>= 1) m = fmaxf(m, __shfl_xor_sync(0xffffffffu, m, off));
    float e = expf(v0 - m) + ((lane < 8) ? expf(v1 - m) : 0.f);
#pragma unroll
    for (int off = 16; off; off >>= 1) e += __shfl_xor_sync(0xffffffffu, e, off);
    float lse = m + logf(e);
    out[(size_t)n * 40 + lane] = v0 - lse;
    if (lane < 8) out[(size_t)n * 40 + lane + 32] = v1 - lse;
}

// ---------------- launch -----------------------------------------------------
extern "C" void kernel_launch(void* const* d_in, const int* in_sizes, int n_in,
                              void* d_out, int out_size) {
    const float* x    = (const float*)d_in[0];
    const int*   adj  = (const int*)d_in[1];
    const float* W1   = (const float*)d_in[2];
    const float* a1   = (const float*)d_in[3];
    const float* W2   = (const float*)d_in[4];
    const float* a2   = (const float*)d_in[5];
    const float* W3   = (const float*)d_in[6];
    const float* a3   = (const float*)d_in[7];
    const float* Wlin = (const float*)d_in[8];
    const float* blin = (const float*)d_in[9];
    float* out = (float*)d_out;

    __half *x16, *W16, *h1h, *h2h, *h3h;
    cudaGetSymbolAddress((void**)&x16, g_x16);
    cudaGetSymbolAddress((void**)&W16, g_W16);
    cudaGetSymbolAddress((void**)&h1h, g_h1h);
    cudaGetSymbolAddress((void**)&h2h, g_h2h);
    cudaGetSymbolAddress((void**)&h3h, g_h3h);

    pack_mask_kernel<<<(Nn * NWORDS) / 256, 256>>>(adj);
    f2h_kernel<<<(Nn * 512 / 4 + 255) / 256, 256>>>(x, x16, Nn * 512 / 4);
    f2h_kernel<<<(131072 / 4 + 255) / 256, 256>>>(W1, W16, 131072 / 4);
    f2h_kernel<<<(32768 / 4 + 255) / 256, 256>>>(W2, W16 + W2_OFF, 32768 / 4);
    f2h_kernel<<<(8192 / 4 + 255) / 256, 256>>>(W3, W16 + W3_OFF, 8192 / 4);

    dim3 grid(Nn / 64, Hh);

    // stage 1: Fin=512, O=64
    gemm_mma_kernel<512, 64, 512><<<grid, 512>>>(x16, W16, a1);
    agg_mma_kernel<64, 512><<<grid, 512>>>(h1h, 256);

    // stage 2: Fin=256, O=32
    gemm_mma_kernel<256, 32, 512><<<grid, 512>>>(h1h, W16 + W2_OFF, a2);
    agg_mma_kernel<32, 512><<<grid, 512>>>(h2h, 128);

    // stage 3: Fin=128, O=16
    gemm_mma_kernel<128, 16, 256><<<grid, 256>>>(h2h, W16 + W3_OFF, a3);
    agg_mma_kernel<16, 256><<<grid, 256>>>(h3h, 64);

    final_kernel<<<(Nn * 32) / 256, 256>>>(Wlin, blin, out);
}